// round 1
// baseline (speedup 1.0000x reference)
#include <cuda_runtime.h>

#define BH     16       // b*h
#define HEADS  8
#define NSEQ   8192
#define DH     64
#define MLAND  256
#define MMSZ   (MLAND*MLAND)   // 65536

// ---------------- device scratch (no allocations allowed) ----------------
__device__ float g_qland[BH*MLAND*DH];
__device__ float g_kland[BH*MLAND*DH];
__device__ float g_mm[6ll*BH*MMSZ];     // X, ZA, ZB, A, T, U  (6 x 4MB)
__device__ float g_p3v[BH*MLAND*DH];    // softmax(sim3) @ v
__device__ float g_W[BH*MLAND*DH];      // attn2_inv @ p3v
__device__ int   g_maxcs, g_maxrs;      // global maxes for pinv z-init

#define IX  0
#define IZA 1
#define IZB 2
#define IA  3
#define IT  4
#define IU  5

// ---------------- kernel 1: landmarks (mean over groups of 32) ----------------
__global__ void k_landmarks(const float* __restrict__ q, const float* __restrict__ k) {
    int m = blockIdx.x, bh = blockIdx.y;
    const float* src = blockIdx.z ? k : q;
    float* dst = blockIdx.z ? g_kland : g_qland;
    int j = threadIdx.x;  // 64
    const float* p = src + ((size_t)bh*NSEQ + (size_t)m*32)*DH + j;
    float s = 0.f;
#pragma unroll
    for (int r = 0; r < 32; r++) s += p[r*DH];
    dst[(bh*MLAND + m)*DH + j] = s * (1.f/32.f);
    if (blockIdx.z == 0 && m == 0 && bh == 0 && j == 0) { g_maxcs = 0; g_maxrs = 0; }
}

// ---------------- kernel 2: attn2 = softmax(q_land @ k_land^T) ----------------
// grid (8, BH), 256 threads, dyn smem: kland[256][68] + qtile[32][68]
#define SMEM_ATTN2 ((256*68 + 32*68)*4)
__global__ void k_attn2() {
    extern __shared__ float sm[];
    float* kl = sm;               // 256 x 68
    float* ql = sm + 256*68;      // 32 x 68
    int bh = blockIdx.y, r0 = blockIdx.x*32, t = threadIdx.x;
    const float4* ks = (const float4*)(g_kland + (size_t)bh*MLAND*DH);
    for (int i = t; i < 256*16; i += 256) { int row=i>>4, c=i&15; *(float4*)(kl+row*68+c*4) = ks[row*16+c]; }
    const float4* qs = (const float4*)(g_qland + ((size_t)bh*MLAND + r0)*DH);
    for (int i = t; i < 32*16; i += 256)  { int row=i>>4, c=i&15; *(float4*)(ql+row*68+c*4) = qs[row*16+c]; }
    __syncthreads();
    int r = t >> 3, j8 = t & 7;
    float acc[32];
#pragma unroll
    for (int c = 0; c < 32; c++) acc[c] = 0.f;
    for (int kk = 0; kk < 64; kk += 4) {
        float4 qv = *(float4*)(ql + r*68 + kk);
#pragma unroll
        for (int c = 0; c < 32; c++) {
            float4 kv = *(float4*)(kl + (j8 + 8*c)*68 + kk);
            acc[c] += qv.x*kv.x + qv.y*kv.y + qv.z*kv.z + qv.w*kv.w;
        }
    }
    float mx = -1e30f;
#pragma unroll
    for (int c = 0; c < 32; c++) mx = fmaxf(mx, acc[c]);
#pragma unroll
    for (int o = 4; o; o >>= 1) mx = fmaxf(mx, __shfl_xor_sync(0xffffffffu, mx, o, 8));
    float sum = 0.f;
#pragma unroll
    for (int c = 0; c < 32; c++) { acc[c] = __expf(acc[c] - mx); sum += acc[c]; }
#pragma unroll
    for (int o = 4; o; o >>= 1) sum += __shfl_xor_sync(0xffffffffu, sum, o, 8);
    float inv = 1.f / sum;
    float* X = g_mm + (size_t)IX*BH*MMSZ + (size_t)bh*MMSZ + (size_t)(r0 + r)*MLAND;
#pragma unroll
    for (int c = 0; c < 32; c++) X[j8 + 8*c] = acc[c] * inv;
}

// ---------------- kernel 3: global max col-sum / row-sum of attn2 ----------------
__global__ void k_colrow() {
    int bh = blockIdx.x, t = threadIdx.x;
    const float* x = g_mm + (size_t)IX*BH*MMSZ + (size_t)bh*MMSZ;
    float cs = 0.f, rs = 0.f;
    for (int i = 0; i < 256; i++) cs += x[i*256 + t];   // column sum (col t)
    for (int j = 0; j < 256; j++) rs += x[t*256 + j];   // row sum (row t)
#pragma unroll
    for (int o = 16; o; o >>= 1) {
        cs = fmaxf(cs, __shfl_xor_sync(0xffffffffu, cs, o));
        rs = fmaxf(rs, __shfl_xor_sync(0xffffffffu, rs, o));
    }
    __shared__ float sc[8], sr[8];
    if ((t & 31) == 0) { sc[t>>5] = cs; sr[t>>5] = rs; }
    __syncthreads();
    if (t == 0) {
        float mc = sc[0], mr = sr[0];
        for (int w = 1; w < 8; w++) { mc = fmaxf(mc, sc[w]); mr = fmaxf(mr, sr[w]); }
        atomicMax(&g_maxcs, __float_as_int(mc));
        atomicMax(&g_maxrs, __float_as_int(mr));
    }
}

// ---------------- kernel 4: z0 = x^T / (max_rowsum * max_colsum) ----------------
__global__ void k_zinit() {
    float s = 1.f / (__int_as_float(g_maxcs) * __int_as_float(g_maxrs));
    int bh = blockIdx.y;
    int idx = blockIdx.x*256 + threadIdx.x;    // 0..65535
    int i = idx >> 8, j = idx & 255;
    const float* X = g_mm + (size_t)IX*BH*MMSZ  + (size_t)bh*MMSZ;
    float*       Z = g_mm + (size_t)IZA*BH*MMSZ + (size_t)bh*MMSZ;
    Z[i*256 + j] = X[j*256 + i] * s;
}

// ---------------- batched SGEMM: Out = alpha*P + beta*(P @ Q) ----------------
// P: [BH][256][256], Q/Out: [BH][256][NQ].  64x64 tile, BK=16, 4x4 microtile.
template<int NQ>
__global__ void k_gemm(const float* __restrict__ Pg, const float* __restrict__ Qg,
                       float* __restrict__ Og, float alpha, float beta) {
    __shared__ float sA[16][68];
    __shared__ float sB[16][68];
    int bh = blockIdx.z;
    const float* P = Pg + (size_t)bh*MMSZ;
    const float* Q = Qg + (size_t)bh*256*NQ;
    float*       O = Og + (size_t)bh*256*NQ;
    int i0 = blockIdx.y*64, j0 = blockIdx.x*64;
    int t = threadIdx.x, tx = t & 15, ty = t >> 4;
    float acc[4][4];
#pragma unroll
    for (int a = 0; a < 4; a++)
#pragma unroll
        for (int b = 0; b < 4; b++) acc[a][b] = 0.f;
    int la_i = t >> 2, la_k = (t & 3)*4;
    int lb_k = t >> 4, lb_j = (t & 15)*4;
    for (int k0 = 0; k0 < 256; k0 += 16) {
        float4 av = *(const float4*)(P + (size_t)(i0 + la_i)*256 + k0 + la_k);
        float4 bv = *(const float4*)(Q + (size_t)(k0 + lb_k)*NQ + j0 + lb_j);
        __syncthreads();
        sA[la_k  ][la_i] = av.x; sA[la_k+1][la_i] = av.y;
        sA[la_k+2][la_i] = av.z; sA[la_k+3][la_i] = av.w;
        *(float4*)(&sB[lb_k][lb_j]) = bv;
        __syncthreads();
#pragma unroll
        for (int k = 0; k < 16; k++) {
            float4 a = *(float4*)(&sA[k][ty*4]);
            float4 b = *(float4*)(&sB[k][tx*4]);
            float ar[4] = {a.x, a.y, a.z, a.w};
            float br[4] = {b.x, b.y, b.z, b.w};
#pragma unroll
            for (int ii = 0; ii < 4; ii++)
#pragma unroll
                for (int jj = 0; jj < 4; jj++) acc[ii][jj] += ar[ii]*br[jj];
        }
    }
#pragma unroll
    for (int ii = 0; ii < 4; ii++) {
        int i = i0 + ty*4 + ii;
        float4 o;
        o.x = beta*acc[ii][0]; o.y = beta*acc[ii][1];
        o.z = beta*acc[ii][2]; o.w = beta*acc[ii][3];
        if (alpha != 0.f) {
            float4 pv = *(const float4*)(P + (size_t)i*256 + j0 + tx*4);
            o.x += alpha*pv.x; o.y += alpha*pv.y; o.z += alpha*pv.z; o.w += alpha*pv.w;
        }
        *(float4*)(O + (size_t)i*NQ + j0 + tx*4) = o;
    }
}

// ---------------- kernel 5: p3v = softmax(q_land @ k^T) @ v, flash-style ----------------
// grid (16, BH): block handles 16 landmark rows, streams k/v in 64-row chunks.
__global__ void k_attn3v(const float* __restrict__ k, const float* __restrict__ v) {
    __shared__ float ks[64][68];
    __shared__ float vs[64][68];
    __shared__ float qs[16][68];
    __shared__ float sp[16][68];
    int bh = blockIdx.y, m0 = blockIdx.x*16, t = threadIdx.x;
    int r = t >> 4, q16 = t & 15;
    for (int i = t; i < 16*16; i += 256) {
        int row = i >> 4, c = i & 15;
        *(float4*)(&qs[row][c*4]) = ((const float4*)(g_qland + ((size_t)bh*MLAND + m0 + row)*DH))[c];
    }
    float m_run = -1e30f, l_run = 0.f;
    float acc[4] = {0.f, 0.f, 0.f, 0.f};
    const float* kb = k + (size_t)bh*NSEQ*DH;
    const float* vb = v + (size_t)bh*NSEQ*DH;
    __syncthreads();
    for (int n0 = 0; n0 < NSEQ; n0 += 64) {
        for (int i = t; i < 64*16; i += 256) {
            int row = i >> 4, c = i & 15;
            *(float4*)(&ks[row][c*4]) = ((const float4*)(kb + (size_t)(n0+row)*DH))[c];
            *(float4*)(&vs[row][c*4]) = ((const float4*)(vb + (size_t)(n0+row)*DH))[c];
        }
        __syncthreads();
        float sv[4] = {0.f, 0.f, 0.f, 0.f};
        for (int kk = 0; kk < 64; kk += 4) {
            float4 qv = *(float4*)(&qs[r][kk]);
#pragma unroll
            for (int c = 0; c < 4; c++) {
                float4 kv = *(float4*)(&ks[q16*4 + c][kk]);
                sv[c] += qv.x*kv.x + qv.y*kv.y + qv.z*kv.z + qv.w*kv.w;
            }
        }
        float mx = fmaxf(fmaxf(sv[0], sv[1]), fmaxf(sv[2], sv[3]));
#pragma unroll
        for (int o = 8; o; o >>= 1) mx = fmaxf(mx, __shfl_xor_sync(0xffffffffu, mx, o, 16));
        float m_new = fmaxf(m_run, mx);
        float corr = __expf(m_run - m_new);
        float ls = 0.f;
#pragma unroll
        for (int c = 0; c < 4; c++) { sv[c] = __expf(sv[c] - m_new); ls += sv[c]; }
#pragma unroll
        for (int o = 8; o; o >>= 1) ls += __shfl_xor_sync(0xffffffffu, ls, o, 16);
        l_run = l_run*corr + ls;
        m_run = m_new;
#pragma unroll
        for (int c = 0; c < 4; c++) acc[c] *= corr;
        *(float4*)(&sp[r][q16*4]) = make_float4(sv[0], sv[1], sv[2], sv[3]);
        __syncthreads();
        for (int kk = 0; kk < 64; kk++) {
            float pk = sp[r][kk];
            float4 vv = *(float4*)(&vs[kk][q16*4]);
            acc[0] += pk*vv.x; acc[1] += pk*vv.y; acc[2] += pk*vv.z; acc[3] += pk*vv.w;
        }
        __syncthreads();
    }
    float inv = 1.f / l_run;
    *(float4*)(g_p3v + ((size_t)bh*MLAND + m0 + r)*DH + q16*4) =
        make_float4(acc[0]*inv, acc[1]*inv, acc[2]*inv, acc[3]*inv);
}

// ---------------- kernel 6: out = softmax(q @ k_land^T) @ W + depthwise_conv(v) ----------------
// grid (256, BH): block handles 32 q rows. dyn smem: kl[256][68] (reused for W, v) + ql[32][68] + p[32][264]
#define SMEM_F1 ((256*68 + 32*68 + 32*264)*4)
__global__ void k_fused1(const float* __restrict__ q, const float* __restrict__ v,
                         const float* __restrict__ cw, float* __restrict__ out) {
    extern __shared__ float sm[];
    float* kl = sm;                        // 256 x 68 (kland -> W -> v tile)
    float* ql = sm + 256*68;               // 32 x 68  (q tile -> conv weights)
    float* ss = sm + 256*68 + 32*68;       // 32 x 264 (softmax probs)
    int bh = blockIdx.y, g0 = blockIdx.x*32, t = threadIdx.x;
    int r = t >> 3, j8 = t & 7;
    const float4* ksrc = (const float4*)(g_kland + (size_t)bh*MLAND*DH);
    for (int i = t; i < 256*16; i += 256) { int row=i>>4, c=i&15; *(float4*)(kl+row*68+c*4) = ksrc[row*16+c]; }
    const float4* qsrc = (const float4*)(q + ((size_t)bh*NSEQ + g0)*DH);
    for (int i = t; i < 32*16; i += 256)  { int row=i>>4, c=i&15; *(float4*)(ql+row*68+c*4) = qsrc[row*16+c]; }
    __syncthreads();
    float acc[32];
#pragma unroll
    for (int c = 0; c < 32; c++) acc[c] = 0.f;
    for (int kk = 0; kk < 64; kk += 4) {
        float4 qv = *(float4*)(ql + r*68 + kk);
#pragma unroll
        for (int c = 0; c < 32; c++) {
            float4 kv = *(float4*)(kl + (j8 + 8*c)*68 + kk);
            acc[c] += qv.x*kv.x + qv.y*kv.y + qv.z*kv.z + qv.w*kv.w;
        }
    }
    float mx = -1e30f;
#pragma unroll
    for (int c = 0; c < 32; c++) mx = fmaxf(mx, acc[c]);
#pragma unroll
    for (int o = 4; o; o >>= 1) mx = fmaxf(mx, __shfl_xor_sync(0xffffffffu, mx, o, 8));
    float sum = 0.f;
#pragma unroll
    for (int c = 0; c < 32; c++) { acc[c] = __expf(acc[c] - mx); sum += acc[c]; }
#pragma unroll
    for (int o = 4; o; o >>= 1) sum += __shfl_xor_sync(0xffffffffu, sum, o, 8);
    float inv = 1.f / sum;
#pragma unroll
    for (int c = 0; c < 32; c++) ss[r*264 + j8 + 8*c] = acc[c] * inv;
    __syncthreads();
    // reload kl with W
    const float4* wsrc = (const float4*)(g_W + (size_t)bh*MLAND*DH);
    for (int i = t; i < 256*16; i += 256) { int row=i>>4, c=i&15; *(float4*)(kl+row*68+c*4) = wsrc[row*16+c]; }
    __syncthreads();
    float oacc[8];
#pragma unroll
    for (int c = 0; c < 8; c++) oacc[c] = 0.f;
    int col = j8*8;
    const float* srow = ss + r*264;
#pragma unroll 8
    for (int kk = 0; kk < 256; kk++) {
        float pk = srow[kk];
        float4 w0 = *(float4*)(kl + kk*68 + col);
        float4 w1 = *(float4*)(kl + kk*68 + col + 4);
        oacc[0] += pk*w0.x; oacc[1] += pk*w0.y; oacc[2] += pk*w0.z; oacc[3] += pk*w0.w;
        oacc[4] += pk*w1.x; oacc[5] += pk*w1.y; oacc[6] += pk*w1.z; oacc[7] += pk*w1.w;
    }
    __syncthreads();
    // conv: load v rows [g0-16, g0+48) into kl, weights into ql
    const float* vb = v + (size_t)bh*NSEQ*DH;
    for (int i = t; i < 64*16; i += 256) {
        int row = i >> 4, c = i & 15, gr = g0 - 16 + row;
        float4 val = make_float4(0.f, 0.f, 0.f, 0.f);
        if (gr >= 0 && gr < NSEQ) val = *(const float4*)(vb + (size_t)gr*DH + c*4);
        *(float4*)(kl + row*68 + c*4) = val;
    }
    if (t < 33) ql[t] = cw[(bh & 7)*33 + t];
    __syncthreads();
    float res[8];
#pragma unroll
    for (int c = 0; c < 8; c++) res[c] = 0.f;
#pragma unroll
    for (int tt = 0; tt < 33; tt++) {
        float w = ql[tt];
        float4 v0 = *(float4*)(kl + (r + tt)*68 + col);
        float4 v1 = *(float4*)(kl + (r + tt)*68 + col + 4);
        res[0] += w*v0.x; res[1] += w*v0.y; res[2] += w*v0.z; res[3] += w*v0.w;
        res[4] += w*v1.x; res[5] += w*v1.y; res[6] += w*v1.z; res[7] += w*v1.w;
    }
    float* ob = out + ((size_t)bh*NSEQ + g0 + r)*DH + col;
    *(float4*)ob       = make_float4(oacc[0]+res[0], oacc[1]+res[1], oacc[2]+res[2], oacc[3]+res[3]);
    *(float4*)(ob + 4) = make_float4(oacc[4]+res[4], oacc[5]+res[5], oacc[6]+res[6], oacc[7]+res[7]);
}

// ---------------- launcher ----------------
extern "C" void kernel_launch(void* const* d_in, const int* in_sizes, int n_in,
                              void* d_out, int out_size) {
    (void)in_sizes; (void)n_in; (void)out_size;
    const float* q  = (const float*)d_in[0];
    const float* k  = (const float*)d_in[1];
    const float* v  = (const float*)d_in[2];
    const float* cw = (const float*)d_in[3];
    float* out = (float*)d_out;

    cudaFuncSetAttribute(k_attn2,  cudaFuncAttributeMaxDynamicSharedMemorySize, SMEM_ATTN2);
    cudaFuncSetAttribute(k_fused1, cudaFuncAttributeMaxDynamicSharedMemorySize, SMEM_F1);

    float *mm, *p3v, *W;
    cudaGetSymbolAddress((void**)&mm,  g_mm);
    cudaGetSymbolAddress((void**)&p3v, g_p3v);
    cudaGetSymbolAddress((void**)&W,   g_W);

    k_landmarks<<<dim3(MLAND, BH, 2), 64>>>(q, k);
    k_attn2<<<dim3(8, BH), 256, SMEM_ATTN2>>>();
    k_colrow<<<BH, 256>>>();
    k_zinit<<<dim3(256, BH), 256>>>();
    k_attn3v<<<dim3(16, BH), 256>>>(k, v);

    const size_t S = (size_t)BH * MMSZ;
    float *X = mm + IX*S, *ZA = mm + IZA*S, *ZB = mm + IZB*S;
    float *A = mm + IA*S, *T  = mm + IT*S,  *U  = mm + IU*S;
    dim3 gg(4, 4, BH);
    float *zi = ZA, *zo = ZB;
    for (int it = 0; it < 6; it++) {
        k_gemm<256><<<gg, 256>>>(X,  zi, A,  0.f,   1.f);    // A = x@z
        k_gemm<256><<<gg, 256>>>(A,  A,  T,  7.f,  -1.f);    // T = 7A - A@A       = A@(7I-A)
        k_gemm<256><<<gg, 256>>>(A,  T,  U,  15.f, -1.f);    // U = 15A - A@T      = A@(15I-T)
        k_gemm<256><<<gg, 256>>>(zi, U,  zo, 3.25f, -0.25f); // z' = 3.25z - .25z@U = .25 z@(13I-U)
        float* tmp = zi; zi = zo; zo = tmp;
    }
    k_gemm<64><<<dim3(1, 4, BH), 256>>>(zi, p3v, W, 0.f, 1.f);  // W = z_final @ p3v
    k_fused1<<<dim3(256, BH), 256, SMEM_F1>>>(q, v, cw, out);
}

// round 4
// speedup vs baseline: 1.7611x; 1.7611x over previous
#include <cuda_runtime.h>

#define BH     16       // b*h
#define HEADS  8
#define NSEQ   8192
#define DH     64
#define MLAND  256
#define MMSZ   (MLAND*MLAND)   // 65536
#define SPLITS 4

// ---------------- device scratch ----------------
__device__ float g_qland[BH*MLAND*DH];
__device__ float g_kland[BH*MLAND*DH];
__device__ float g_mm[6ll*BH*MMSZ];                 // X, A, T, V, ZA, ZB
__device__ float g_p3v[BH*MLAND*DH];                // softmax(sim3) @ v (combined)
__device__ float g_p3vp[(size_t)SPLITS*BH*MLAND*DH];// split partials
__device__ float g_mlp[(size_t)SPLITS*BH*MLAND*2];  // split (m, l)
__device__ float g_W[BH*MLAND*DH];                  // attn2_inv @ p3v
__device__ int   g_maxcs, g_maxrs;

#define IX  0
#define IA  1
#define IT  2
#define IV  3
#define IZA 4
#define IZB 5

// ---------------- kernel 1: landmarks ----------------
__global__ void k_landmarks(const float* __restrict__ q, const float* __restrict__ k) {
    int m = blockIdx.x, bh = blockIdx.y;
    const float* src = blockIdx.z ? k : q;
    float* dst = blockIdx.z ? g_kland : g_qland;
    int j = threadIdx.x;  // 64
    const float* p = src + ((size_t)bh*NSEQ + (size_t)m*32)*DH + j;
    float s = 0.f;
#pragma unroll
    for (int r = 0; r < 32; r++) s += p[r*DH];
    dst[(bh*MLAND + m)*DH + j] = s * (1.f/32.f);
    if (blockIdx.z == 0 && m == 0 && bh == 0 && j == 0) { g_maxcs = 0; g_maxrs = 0; }
}

// ---------------- kernel 2: attn2 = softmax(q_land @ k_land^T) ----------------
#define SMEM_ATTN2 ((256*68 + 32*68)*4)
__global__ void k_attn2() {
    extern __shared__ float sm[];
    float* kl = sm;               // 256 x 68
    float* ql = sm + 256*68;      // 32 x 68
    int bh = blockIdx.y, r0 = blockIdx.x*32, t = threadIdx.x;
    const float4* ks = (const float4*)(g_kland + (size_t)bh*MLAND*DH);
    for (int i = t; i < 256*16; i += 256) { int row=i>>4, c=i&15; *(float4*)(kl+row*68+c*4) = ks[row*16+c]; }
    const float4* qs = (const float4*)(g_qland + ((size_t)bh*MLAND + r0)*DH);
    for (int i = t; i < 32*16; i += 256)  { int row=i>>4, c=i&15; *(float4*)(ql+row*68+c*4) = qs[row*16+c]; }
    __syncthreads();
    int r = t >> 3, j8 = t & 7;
    float acc[32];
#pragma unroll
    for (int c = 0; c < 32; c++) acc[c] = 0.f;
    for (int kk = 0; kk < 64; kk += 4) {
        float4 qv = *(float4*)(ql + r*68 + kk);
#pragma unroll
        for (int c = 0; c < 32; c++) {
            float4 kv = *(float4*)(kl + (j8 + 8*c)*68 + kk);
            acc[c] += qv.x*kv.x + qv.y*kv.y + qv.z*kv.z + qv.w*kv.w;
        }
    }
    float mx = -1e30f;
#pragma unroll
    for (int c = 0; c < 32; c++) mx = fmaxf(mx, acc[c]);
#pragma unroll
    for (int o = 4; o; o >>= 1) mx = fmaxf(mx, __shfl_xor_sync(0xffffffffu, mx, o, 8));
    float sum = 0.f;
#pragma unroll
    for (int c = 0; c < 32; c++) { acc[c] = __expf(acc[c] - mx); sum += acc[c]; }
#pragma unroll
    for (int o = 4; o; o >>= 1) sum += __shfl_xor_sync(0xffffffffu, sum, o, 8);
    float inv = 1.f / sum;
    float* X = g_mm + (size_t)IX*BH*MMSZ + (size_t)bh*MMSZ + (size_t)(r0 + r)*MLAND;
#pragma unroll
    for (int c = 0; c < 32; c++) X[j8 + 8*c] = acc[c] * inv;
}

// ---------------- kernel 3: global max col-sum / row-sum of attn2 ----------------
__global__ void k_colrow() {
    int bh = blockIdx.x, t = threadIdx.x;
    const float* x = g_mm + (size_t)IX*BH*MMSZ + (size_t)bh*MMSZ;
    float cs = 0.f, rs = 0.f;
    for (int i = 0; i < 256; i++) cs += x[i*256 + t];
    for (int j = 0; j < 256; j++) rs += x[t*256 + j];
#pragma unroll
    for (int o = 16; o; o >>= 1) {
        cs = fmaxf(cs, __shfl_xor_sync(0xffffffffu, cs, o));
        rs = fmaxf(rs, __shfl_xor_sync(0xffffffffu, rs, o));
    }
    __shared__ float sc[8], sr[8];
    if ((t & 31) == 0) { sc[t>>5] = cs; sr[t>>5] = rs; }
    __syncthreads();
    if (t == 0) {
        float mc = sc[0], mr = sr[0];
        for (int w = 1; w < 8; w++) { mc = fmaxf(mc, sc[w]); mr = fmaxf(mr, sr[w]); }
        atomicMax(&g_maxcs, __float_as_int(mc));
        atomicMax(&g_maxrs, __float_as_int(mr));
    }
}

// ================= double-buffered 64x64 SGEMM core =================
// Out = alpha*P + beta*(P@Q) + diag*I   (P:[256,256], Q/Out:[256,NQ])
template<int NQ>
__global__ void k_gemm2(const float* __restrict__ Pg, const float* __restrict__ Qg,
                        float* __restrict__ Og, float alpha, float beta, float diag) {
    __shared__ float sA[2][16][68];
    __shared__ float sB[2][16][68];
    int bh = blockIdx.z;
    const float* P = Pg + (size_t)bh*MMSZ;
    const float* Q = Qg + (size_t)bh*256*NQ;
    float*       O = Og + (size_t)bh*256*NQ;
    int i0 = blockIdx.y*64, j0 = blockIdx.x*64;
    int t = threadIdx.x, tx = t & 15, ty = t >> 4;
    int la_i = t >> 2, la_k = (t & 3)*4;
    int lb_k = t >> 4, lb_j = (t & 15)*4;
    const float* pA = P + (size_t)(i0 + la_i)*256 + la_k;
    const float* pB = Q + (size_t)lb_k*NQ + j0 + lb_j;
    float4 av = *(const float4*)pA;
    float4 bv = *(const float4*)pB;
    sA[0][la_k  ][la_i] = av.x; sA[0][la_k+1][la_i] = av.y;
    sA[0][la_k+2][la_i] = av.z; sA[0][la_k+3][la_i] = av.w;
    *(float4*)&sB[0][lb_k][lb_j] = bv;
    __syncthreads();
    float acc[4][4];
#pragma unroll
    for (int a = 0; a < 4; a++)
#pragma unroll
        for (int b = 0; b < 4; b++) acc[a][b] = 0.f;
    for (int s = 0; s < 16; s++) {
        int cur = s & 1;
        if (s < 15) {
            av = *(const float4*)(pA + (s+1)*16);
            bv = *(const float4*)(pB + (size_t)(s+1)*16*NQ);
        }
#pragma unroll
        for (int k = 0; k < 16; k++) {
            float4 a = *(float4*)&sA[cur][k][ty*4];
            float4 b = *(float4*)&sB[cur][k][tx*4];
            float ar[4] = {a.x,a.y,a.z,a.w}, br[4] = {b.x,b.y,b.z,b.w};
#pragma unroll
            for (int ii = 0; ii < 4; ii++)
#pragma unroll
                for (int jj = 0; jj < 4; jj++) acc[ii][jj] += ar[ii]*br[jj];
        }
        if (s < 15) {
            int nxt = cur ^ 1;
            sA[nxt][la_k  ][la_i] = av.x; sA[nxt][la_k+1][la_i] = av.y;
            sA[nxt][la_k+2][la_i] = av.z; sA[nxt][la_k+3][la_i] = av.w;
            *(float4*)&sB[nxt][lb_k][lb_j] = bv;
            __syncthreads();
        }
    }
#pragma unroll
    for (int ii = 0; ii < 4; ii++) {
        int i = i0 + ty*4 + ii;
        float o[4];
#pragma unroll
        for (int jj = 0; jj < 4; jj++) o[jj] = beta*acc[ii][jj];
        if (alpha != 0.f) {
            float4 pv = *(const float4*)(P + (size_t)i*256 + j0 + tx*4);
            o[0] += alpha*pv.x; o[1] += alpha*pv.y; o[2] += alpha*pv.z; o[3] += alpha*pv.w;
        }
        if (diag != 0.f) {
#pragma unroll
            for (int jj = 0; jj < 4; jj++) if (i == j0 + tx*4 + jj) o[jj] += diag;
        }
        *(float4*)(O + (size_t)i*NQ + j0 + tx*4) = make_float4(o[0], o[1], o[2], o[3]);
    }
}

// A = s * (X @ X^T)
__global__ void k_gemm_xxt(const float* __restrict__ Xg, float* __restrict__ Og) {
    __shared__ float sA[2][16][68];
    __shared__ float sB[2][16][68];
    float s = 1.f / (__int_as_float(g_maxcs) * __int_as_float(g_maxrs));
    int bh = blockIdx.z;
    const float* X = Xg + (size_t)bh*MMSZ;
    float*       O = Og + (size_t)bh*MMSZ;
    int i0 = blockIdx.y*64, j0 = blockIdx.x*64;
    int t = threadIdx.x, tx = t & 15, ty = t >> 4;
    int la_i = t >> 2, la_k = (t & 3)*4;
    const float* pA = X + (size_t)(i0 + la_i)*256 + la_k;
    const float* pB = X + (size_t)(j0 + la_i)*256 + la_k;
    float4 av = *(const float4*)pA;
    float4 bv = *(const float4*)pB;
    sA[0][la_k][la_i]=av.x; sA[0][la_k+1][la_i]=av.y; sA[0][la_k+2][la_i]=av.z; sA[0][la_k+3][la_i]=av.w;
    sB[0][la_k][la_i]=bv.x; sB[0][la_k+1][la_i]=bv.y; sB[0][la_k+2][la_i]=bv.z; sB[0][la_k+3][la_i]=bv.w;
    __syncthreads();
    float acc[4][4];
#pragma unroll
    for (int a = 0; a < 4; a++)
#pragma unroll
        for (int b = 0; b < 4; b++) acc[a][b] = 0.f;
    for (int st = 0; st < 16; st++) {
        int cur = st & 1;
        if (st < 15) { av = *(const float4*)(pA + (st+1)*16); bv = *(const float4*)(pB + (st+1)*16); }
#pragma unroll
        for (int k = 0; k < 16; k++) {
            float4 a = *(float4*)&sA[cur][k][ty*4];
            float4 b = *(float4*)&sB[cur][k][tx*4];
            float ar[4] = {a.x,a.y,a.z,a.w}, br[4] = {b.x,b.y,b.z,b.w};
#pragma unroll
            for (int ii = 0; ii < 4; ii++)
#pragma unroll
                for (int jj = 0; jj < 4; jj++) acc[ii][jj] += ar[ii]*br[jj];
        }
        if (st < 15) {
            int nxt = cur ^ 1;
            sA[nxt][la_k][la_i]=av.x; sA[nxt][la_k+1][la_i]=av.y; sA[nxt][la_k+2][la_i]=av.z; sA[nxt][la_k+3][la_i]=av.w;
            sB[nxt][la_k][la_i]=bv.x; sB[nxt][la_k+1][la_i]=bv.y; sB[nxt][la_k+2][la_i]=bv.z; sB[nxt][la_k+3][la_i]=bv.w;
            __syncthreads();
        }
    }
#pragma unroll
    for (int ii = 0; ii < 4; ii++) {
        int i = i0 + ty*4 + ii;
        *(float4*)(O + (size_t)i*256 + j0 + tx*4) =
            make_float4(s*acc[ii][0], s*acc[ii][1], s*acc[ii][2], s*acc[ii][3]);
    }
}

// Out = s * (X^T @ V)
__global__ void k_gemm_atx(const float* __restrict__ Xg, const float* __restrict__ Vg,
                           float* __restrict__ Og) {
    __shared__ float sA[2][16][68];
    __shared__ float sB[2][16][68];
    float s = 1.f / (__int_as_float(g_maxcs) * __int_as_float(g_maxrs));
    int bh = blockIdx.z;
    const float* X = Xg + (size_t)bh*MMSZ;
    const float* V = Vg + (size_t)bh*MMSZ;
    float*       O = Og + (size_t)bh*MMSZ;
    int i0 = blockIdx.y*64, j0 = blockIdx.x*64;
    int t = threadIdx.x, tx = t & 15, ty = t >> 4;
    int ka = t >> 4, ia = (t & 15)*4;
    int lb_k = t >> 4, lb_j = (t & 15)*4;
    const float* pA = X + (size_t)ka*256 + i0 + ia;
    const float* pB = V + (size_t)lb_k*256 + j0 + lb_j;
    float4 av = *(const float4*)pA;
    float4 bv = *(const float4*)pB;
    *(float4*)&sA[0][ka][ia] = av;
    *(float4*)&sB[0][lb_k][lb_j] = bv;
    __syncthreads();
    float acc[4][4];
#pragma unroll
    for (int a = 0; a < 4; a++)
#pragma unroll
        for (int b = 0; b < 4; b++) acc[a][b] = 0.f;
    for (int st = 0; st < 16; st++) {
        int cur = st & 1;
        if (st < 15) {
            av = *(const float4*)(pA + (size_t)(st+1)*16*256);
            bv = *(const float4*)(pB + (size_t)(st+1)*16*256);
        }
#pragma unroll
        for (int k = 0; k < 16; k++) {
            float4 a = *(float4*)&sA[cur][k][ty*4];
            float4 b = *(float4*)&sB[cur][k][tx*4];
            float ar[4] = {a.x,a.y,a.z,a.w}, br[4] = {b.x,b.y,b.z,b.w};
#pragma unroll
            for (int ii = 0; ii < 4; ii++)
#pragma unroll
                for (int jj = 0; jj < 4; jj++) acc[ii][jj] += ar[ii]*br[jj];
        }
        if (st < 15) {
            int nxt = cur ^ 1;
            *(float4*)&sA[nxt][ka][ia] = av;
            *(float4*)&sB[nxt][lb_k][lb_j] = bv;
            __syncthreads();
        }
    }
#pragma unroll
    for (int ii = 0; ii < 4; ii++) {
        int i = i0 + ty*4 + ii;
        *(float4*)(O + (size_t)i*256 + j0 + tx*4) =
            make_float4(s*acc[ii][0], s*acc[ii][1], s*acc[ii][2], s*acc[ii][3]);
    }
}

// ---------------- attn3v: split-KV flash, gemm-style tiles ----------------
#define SMEM_A3V (4*64*68*4)
__global__ void k_attn3v(const float* __restrict__ k, const float* __restrict__ v) {
    extern __shared__ float sm[];
    float* sQt = sm;            // [64 d][68] rows
    float* sKt = sm + 64*68;    // [64 d][68] cols
    float* sV  = sm + 2*64*68;  // [64 seq][68 d]
    float* sP  = sm + 3*64*68;  // [64 seq][68 rows]
    int bh = blockIdx.z, m0 = blockIdx.x*64, sp = blockIdx.y;
    int t = threadIdx.x, tx = t & 15, ty = t >> 4;
    for (int i = t; i < 64*16; i += 256) {
        int row = i >> 4, c = i & 15;
        float4 qv = *(const float4*)(g_qland + ((size_t)bh*MLAND + m0 + row)*DH + c*4);
        sQt[(c*4+0)*68 + row] = qv.x; sQt[(c*4+1)*68 + row] = qv.y;
        sQt[(c*4+2)*68 + row] = qv.z; sQt[(c*4+3)*68 + row] = qv.w;
    }
    float m_run[4], l_run[4], acc[4][4];
#pragma unroll
    for (int i = 0; i < 4; i++) {
        m_run[i] = -1e30f; l_run[i] = 0.f;
#pragma unroll
        for (int j = 0; j < 4; j++) acc[i][j] = 0.f;
    }
    const float* kb = k + (size_t)bh*NSEQ*DH;
    const float* vb = v + (size_t)bh*NSEQ*DH;
    int n0base = sp * (NSEQ/SPLITS);
    __syncthreads();
    for (int c0 = 0; c0 < NSEQ/SPLITS; c0 += 64) {
        int n0 = n0base + c0;
        for (int i = t; i < 64*16; i += 256) {
            int row = i >> 4, cc = i & 15;
            float4 kv = *(const float4*)(kb + (size_t)(n0+row)*DH + cc*4);
            sKt[(cc*4+0)*68 + row] = kv.x; sKt[(cc*4+1)*68 + row] = kv.y;
            sKt[(cc*4+2)*68 + row] = kv.z; sKt[(cc*4+3)*68 + row] = kv.w;
            *(float4*)(sV + row*68 + cc*4) = *(const float4*)(vb + (size_t)(n0+row)*DH + cc*4);
        }
        __syncthreads();
        float s4[4][4];
#pragma unroll
        for (int i = 0; i < 4; i++)
#pragma unroll
            for (int j = 0; j < 4; j++) s4[i][j] = 0.f;
        for (int d = 0; d < 64; d++) {
            float4 qv = *(float4*)(sQt + d*68 + ty*4);
            float4 kv = *(float4*)(sKt + d*68 + tx*4);
            float qr[4] = {qv.x,qv.y,qv.z,qv.w}, kr[4] = {kv.x,kv.y,kv.z,kv.w};
#pragma unroll
            for (int i = 0; i < 4; i++)
#pragma unroll
                for (int j = 0; j < 4; j++) s4[i][j] += qr[i]*kr[j];
        }
#pragma unroll
        for (int i = 0; i < 4; i++) {
            float mx = fmaxf(fmaxf(s4[i][0], s4[i][1]), fmaxf(s4[i][2], s4[i][3]));
#pragma unroll
            for (int o = 8; o; o >>= 1) mx = fmaxf(mx, __shfl_xor_sync(0xffffffffu, mx, o, 16));
            float mn = fmaxf(m_run[i], mx);
            float corr = __expf(m_run[i] - mn);
            m_run[i] = mn;
            float ls = 0.f;
#pragma unroll
            for (int j = 0; j < 4; j++) { s4[i][j] = __expf(s4[i][j] - mn); ls += s4[i][j]; }
#pragma unroll
            for (int o = 8; o; o >>= 1) ls += __shfl_xor_sync(0xffffffffu, ls, o, 16);
            l_run[i] = l_run[i]*corr + ls;
#pragma unroll
            for (int j = 0; j < 4; j++) acc[i][j] *= corr;
        }
#pragma unroll
        for (int j = 0; j < 4; j++)
            *(float4*)(sP + (tx*4+j)*68 + ty*4) = make_float4(s4[0][j], s4[1][j], s4[2][j], s4[3][j]);
        __syncthreads();
        for (int kk = 0; kk < 64; kk++) {
            float4 pv = *(float4*)(sP + kk*68 + ty*4);
            float4 vv = *(float4*)(sV + kk*68 + tx*4);
            float pr[4] = {pv.x,pv.y,pv.z,pv.w}, vr[4] = {vv.x,vv.y,vv.z,vv.w};
#pragma unroll
            for (int i = 0; i < 4; i++)
#pragma unroll
                for (int j = 0; j < 4; j++) acc[i][j] += pr[i]*vr[j];
        }
        __syncthreads();
    }
    float* outp = g_p3vp + (((size_t)sp*BH + bh)*MLAND + m0)*DH;
#pragma unroll
    for (int i = 0; i < 4; i++)
        *(float4*)(outp + (size_t)(ty*4+i)*DH + tx*4) =
            make_float4(acc[i][0], acc[i][1], acc[i][2], acc[i][3]);
    if (tx == 0) {
#pragma unroll
        for (int i = 0; i < 4; i++) {
            size_t mi = (((size_t)sp*BH + bh)*MLAND + m0 + ty*4 + i)*2;
            g_mlp[mi] = m_run[i]; g_mlp[mi+1] = l_run[i];
        }
    }
}

__global__ void k_combine() {
    int row = blockIdx.x, bh = blockIdx.y, d = threadIdx.x;
    float m[SPLITS], l[SPLITS];
#pragma unroll
    for (int s = 0; s < SPLITS; s++) {
        size_t mi = (((size_t)s*BH + bh)*MLAND + row)*2;
        m[s] = g_mlp[mi]; l[s] = g_mlp[mi+1];
    }
    float M = m[0];
#pragma unroll
    for (int s = 1; s < SPLITS; s++) M = fmaxf(M, m[s]);
    float L = 0.f, o = 0.f;
#pragma unroll
    for (int s = 0; s < SPLITS; s++) {
        float w = __expf(m[s] - M);
        L += l[s]*w;
        o += g_p3vp[(((size_t)s*BH + bh)*MLAND + row)*DH + d] * w;
    }
    g_p3v[((size_t)bh*MLAND + row)*DH + d] = o / L;
}

// ---------------- fused1: out = softmax(q @ k_land^T) @ W + conv(v) ----------------
#define SMEM_F1 ((256*68 + 32*68 + 32*264)*4)
__global__ void k_fused1(const float* __restrict__ q, const float* __restrict__ v,
                         const float* __restrict__ cw, float* __restrict__ out) {
    extern __shared__ float sm[];
    float* kl = sm;
    float* ql = sm + 256*68;
    float* ss = sm + 256*68 + 32*68;
    int bh = blockIdx.y, g0 = blockIdx.x*32, t = threadIdx.x;
    int r = t >> 3, j8 = t & 7;
    const float4* ksrc = (const float4*)(g_kland + (size_t)bh*MLAND*DH);
    for (int i = t; i < 256*16; i += 256) { int row=i>>4, c=i&15; *(float4*)(kl+row*68+c*4) = ksrc[row*16+c]; }
    const float4* qsrc = (const float4*)(q + ((size_t)bh*NSEQ + g0)*DH);
    for (int i = t; i < 32*16; i += 256)  { int row=i>>4, c=i&15; *(float4*)(ql+row*68+c*4) = qsrc[row*16+c]; }
    __syncthreads();
    float acc[32];
#pragma unroll
    for (int c = 0; c < 32; c++) acc[c] = 0.f;
    for (int kk = 0; kk < 64; kk += 4) {
        float4 qv = *(float4*)(ql + r*68 + kk);
#pragma unroll
        for (int c = 0; c < 32; c++) {
            float4 kv = *(float4*)(kl + (j8 + 8*c)*68 + kk);
            acc[c] += qv.x*kv.x + qv.y*kv.y + qv.z*kv.z + qv.w*kv.w;
        }
    }
    float mx = -1e30f;
#pragma unroll
    for (int c = 0; c < 32; c++) mx = fmaxf(mx, acc[c]);
#pragma unroll
    for (int o = 4; o; o >>= 1) mx = fmaxf(mx, __shfl_xor_sync(0xffffffffu, mx, o, 8));
    float sum = 0.f;
#pragma unroll
    for (int c = 0; c < 32; c++) { acc[c] = __expf(acc[c] - mx); sum += acc[c]; }
#pragma unroll
    for (int o = 4; o; o >>= 1) sum += __shfl_xor_sync(0xffffffffu, sum, o, 8);
    float inv = 1.f / sum;
#pragma unroll
    for (int c = 0; c < 32; c++) ss[r*264 + j8 + 8*c] = acc[c] * inv;
    __syncthreads();
    const float4* wsrc = (const float4*)(g_W + (size_t)bh*MLAND*DH);
    for (int i = t; i < 256*16; i += 256) { int row=i>>4, c=i&15; *(float4*)(kl+row*68+c*4) = wsrc[row*16+c]; }
    __syncthreads();
    float oacc[8];
#pragma unroll
    for (int c = 0; c < 8; c++) oacc[c] = 0.f;
    int col = j8*8;
    const float* srow = ss + r*264;
    for (int kk = 0; kk < 256; kk += 4) {
        float4 p4 = *(float4*)(srow + kk);
        float pk[4] = {p4.x, p4.y, p4.z, p4.w};
#pragma unroll
        for (int u = 0; u < 4; u++) {
            float4 w0 = *(float4*)(kl + (kk+u)*68 + col);
            float4 w1 = *(float4*)(kl + (kk+u)*68 + col + 4);
            oacc[0] += pk[u]*w0.x; oacc[1] += pk[u]*w0.y; oacc[2] += pk[u]*w0.z; oacc[3] += pk[u]*w0.w;
            oacc[4] += pk[u]*w1.x; oacc[5] += pk[u]*w1.y; oacc[6] += pk[u]*w1.z; oacc[7] += pk[u]*w1.w;
        }
    }
    __syncthreads();
    const float* vb = v + (size_t)bh*NSEQ*DH;
    for (int i = t; i < 64*16; i += 256) {
        int row = i >> 4, c = i & 15, gr = g0 - 16 + row;
        float4 val = make_float4(0.f, 0.f, 0.f, 0.f);
        if (gr >= 0 && gr < NSEQ) val = *(const float4*)(vb + (size_t)gr*DH + c*4);
        *(float4*)(kl + row*68 + c*4) = val;
    }
    if (t < 33) ql[t] = cw[(bh & 7)*33 + t];
    __syncthreads();
    float res[8];
#pragma unroll
    for (int c = 0; c < 8; c++) res[c] = 0.f;
#pragma unroll
    for (int tt = 0; tt < 33; tt++) {
        float w = ql[tt];
        float4 v0 = *(float4*)(kl + (r + tt)*68 + col);
        float4 v1 = *(float4*)(kl + (r + tt)*68 + col + 4);
        res[0] += w*v0.x; res[1] += w*v0.y; res[2] += w*v0.z; res[3] += w*v0.w;
        res[4] += w*v1.x; res[5] += w*v1.y; res[6] += w*v1.z; res[7] += w*v1.w;
    }
    float* ob = out + ((size_t)bh*NSEQ + g0 + r)*DH + col;
    *(float4*)ob       = make_float4(oacc[0]+res[0], oacc[1]+res[1], oacc[2]+res[2], oacc[3]+res[3]);
    *(float4*)(ob + 4) = make_float4(oacc[4]+res[4], oacc[5]+res[5], oacc[6]+res[6], oacc[7]+res[7]);
}

// ---------------- launcher ----------------
extern "C" void kernel_launch(void* const* d_in, const int* in_sizes, int n_in,
                              void* d_out, int out_size) {
    (void)in_sizes; (void)n_in; (void)out_size;
    const float* q  = (const float*)d_in[0];
    const float* k  = (const float*)d_in[1];
    const float* v  = (const float*)d_in[2];
    const float* cw = (const float*)d_in[3];
    float* out = (float*)d_out;

    cudaFuncSetAttribute(k_attn2,  cudaFuncAttributeMaxDynamicSharedMemorySize, SMEM_ATTN2);
    cudaFuncSetAttribute(k_attn3v, cudaFuncAttributeMaxDynamicSharedMemorySize, SMEM_A3V);
    cudaFuncSetAttribute(k_fused1, cudaFuncAttributeMaxDynamicSharedMemorySize, SMEM_F1);

    float *mm, *p3v, *W;
    cudaGetSymbolAddress((void**)&mm,  g_mm);
    cudaGetSymbolAddress((void**)&p3v, g_p3v);
    cudaGetSymbolAddress((void**)&W,   g_W);

    const size_t S = (size_t)BH * MMSZ;
    float *X = mm + IX*S, *A = mm + IA*S, *T = mm + IT*S;
    float *V = mm + IV*S, *ZA = mm + IZA*S, *ZB = mm + IZB*S;

    k_landmarks<<<dim3(MLAND, BH, 2), 64>>>(q, k);
    k_attn2<<<dim3(8, BH), 256, SMEM_ATTN2>>>();
    k_colrow<<<BH, 256>>>();

    dim3 gg(4, 4, BH);
    // iteration 1 (z0 = s*X^T folded into transposed GEMMs)
    k_gemm_xxt<<<gg, 256>>>(X, A);                                   // A  = s*X@X^T
    k_gemm2<256><<<gg, 256>>>(A, A, T, 7.f, -1.f, 0.f);              // T  = 7A - A@A
    k_gemm2<256><<<gg, 256>>>(A, T, V, -3.75f, 0.25f, 3.25f);        // V  = 3.25I - 3.75A + .25A@T
    k_gemm_atx<<<gg, 256>>>(X, V, ZA);                               // z1 = s*X^T@V
    float *zi = ZA, *zo = ZB;
    for (int it = 1; it < 6; it++) {
        k_gemm2<256><<<gg, 256>>>(X,  zi, A, 0.f, 1.f, 0.f);
        k_gemm2<256><<<gg, 256>>>(A,  A,  T, 7.f, -1.f, 0.f);
        k_gemm2<256><<<gg, 256>>>(A,  T,  V, -3.75f, 0.25f, 3.25f);
        k_gemm2<256><<<gg, 256>>>(zi, V,  zo, 0.f, 1.f, 0.f);
        float* tmp = zi; zi = zo; zo = tmp;
    }

    k_attn3v<<<dim3(4, SPLITS, BH), 256, SMEM_A3V>>>(k, v);
    k_combine<<<dim3(MLAND, BH), 64>>>();
    k_gemm2<64><<<dim3(1, 4, BH), 256>>>(zi, p3v, W, 0.f, 1.f, 0.f);  // W = z@p3v
    k_fused1<<<dim3(256, BH), 256, SMEM_F1>>>(q, v, cw, out);
}